// round 1
// baseline (speedup 1.0000x reference)
#include <cuda_runtime.h>
#include <cuda_bf16.h>
#include <math.h>

// Problem constants (fixed shapes for this problem)
#define NROW 4096
#define DIM  128
#define NSET 4
#define TOPK 16

// ---------------- device scratch (no allocations allowed) ----------------
__device__ float g_fn[NROW * DIM];                       // normalized feature
__device__ float g_nn[NSET * NROW * DIM];                // normalized negatives
__device__ float g_sims[(size_t)NSET * NROW * NROW];     // similarity matrices (268 MB)
__device__ float g_top[NSET * NROW * TOPK];              // per-row top-k (sorted desc)
__device__ float g_partial[256];                         // block partial sums

// ---------------- kernel 1: L2 normalize (one warp per row) ----------------
__global__ void __launch_bounds__(256) normalize_kernel(const float* __restrict__ f,
                                                        const float* __restrict__ negs) {
    int w    = blockIdx.x * 8 + (threadIdx.x >> 5);
    int lane = threadIdx.x & 31;
    const float* src;
    float* dst;
    if (w < NROW) {
        src = f + (size_t)w * DIM;
        dst = g_fn + (size_t)w * DIM;
    } else {
        int r = w - NROW;
        src = negs + (size_t)r * DIM;
        dst = g_nn + (size_t)r * DIM;
    }
    float4 v = ((const float4*)src)[lane];
    float ss = v.x * v.x + v.y * v.y + v.z * v.z + v.w * v.w;
#pragma unroll
    for (int off = 16; off > 0; off >>= 1)
        ss += __shfl_xor_sync(0xFFFFFFFFu, ss, off);
    float inv = 1.0f / fmaxf(sqrtf(ss), 1e-12f);
    v.x *= inv; v.y *= inv; v.z *= inv; v.w *= inv;
    ((float4*)dst)[lane] = v;
}

// ---------------- kernel 2: tiled fp32 GEMM with mask epilogue ----------------
// grid: (m_tiles=64, n_tiles=64, j=4), block 256 (16x16 threads, 4x4 micro-tile)
__global__ void __launch_bounds__(256) gemm_kernel(const int* __restrict__ targ,
                                                   const int* __restrict__ idxp) {
    __shared__ __align__(16) float fsT[64][68];  // [d][row], padded
    __shared__ __align__(16) float nsT[64][68];  // [d][col], padded

    int j     = blockIdx.z;
    int nbase = blockIdx.y * 64;
    int mbase = blockIdx.x * 64;
    int tid   = threadIdx.x;
    int tx    = tid & 15;
    int ty    = tid >> 4;

    const float* F = g_fn;
    const float* N = g_nn + (size_t)j * NROW * DIM;

    float acc[4][4];
#pragma unroll
    for (int i = 0; i < 4; ++i)
#pragma unroll
        for (int k = 0; k < 4; ++k) acc[i][k] = 0.0f;

#pragma unroll
    for (int c = 0; c < 2; ++c) {  // two 64-wide d-chunks
        // cooperative load: 1024 float4 per operand tile, 4 per thread
#pragma unroll
        for (int i = 0; i < 4; ++i) {
            int e   = tid + 256 * i;   // 0..1023
            int row = e >> 4;
            int d4  = e & 15;
            float4 fv = *(const float4*)&F[(size_t)(nbase + row) * DIM + c * 64 + d4 * 4];
            float4 nv = *(const float4*)&N[(size_t)(mbase + row) * DIM + c * 64 + d4 * 4];
            int d = d4 * 4;
            fsT[d + 0][row] = fv.x; fsT[d + 1][row] = fv.y;
            fsT[d + 2][row] = fv.z; fsT[d + 3][row] = fv.w;
            nsT[d + 0][row] = nv.x; nsT[d + 1][row] = nv.y;
            nsT[d + 2][row] = nv.z; nsT[d + 3][row] = nv.w;
        }
        __syncthreads();

#pragma unroll 8
        for (int d = 0; d < 64; ++d) {
            float4 a = *(const float4*)&fsT[d][ty * 4];
            float4 b = *(const float4*)&nsT[d][tx * 4];
            float av[4] = {a.x, a.y, a.z, a.w};
            float bv[4] = {b.x, b.y, b.z, b.w};
#pragma unroll
            for (int i = 0; i < 4; ++i)
#pragma unroll
                for (int k = 0; k < 4; ++k)
                    acc[i][k] = fmaf(av[i], bv[k], acc[i][k]);
        }
        __syncthreads();
    }

    // epilogue: same-class mask on set idx, store to scratch
    int  idxv   = *idxp;
    bool domask = (j == idxv);
    int tn[4], tm[4];
    if (domask) {
#pragma unroll
        for (int i = 0; i < 4; ++i) {
            tn[i] = targ[nbase + ty * 4 + i];
            tm[i] = targ[mbase + tx * 4 + i];
        }
    }
#pragma unroll
    for (int i = 0; i < 4; ++i) {
        int n = nbase + ty * 4 + i;
        float4 o;
        o.x = acc[i][0]; o.y = acc[i][1]; o.z = acc[i][2]; o.w = acc[i][3];
        if (domask) {
            if (tn[i] == tm[0]) o.x = -1e9f;
            if (tn[i] == tm[1]) o.y = -1e9f;
            if (tn[i] == tm[2]) o.z = -1e9f;
            if (tn[i] == tm[3]) o.w = -1e9f;
        }
        *(float4*)&g_sims[(((size_t)j * NROW + n) << 12) + mbase + tx * 4] = o;
    }
}

// ---------------- kernel 3: per-row top-16 (one warp per (j,n) row) ----------------
__global__ void __launch_bounds__(256) topk_kernel() {
    int w    = blockIdx.x * 8 + (threadIdx.x >> 5);   // 0..16383
    int lane = threadIdx.x & 31;
    const float* row = g_sims + ((size_t)w << 12);

    float t[TOPK];
#pragma unroll
    for (int s = 0; s < TOPK; ++s) t[s] = -INFINITY;

    // each lane streams 128 values (coalesced), keeps local sorted-16
    for (int i = 0; i < 128; ++i) {
        float v = row[i * 32 + lane];
        if (v > t[TOPK - 1]) {
#pragma unroll
            for (int s = TOPK - 1; s >= 1; --s)
                t[s] = (v > t[s]) ? ((v > t[s - 1]) ? t[s - 1] : v) : t[s];
            t[0] = fmaxf(t[0], v);
        }
    }

    // warp merge: 16 rounds of max over the lane heads
    for (int it = 0; it < TOPK; ++it) {
        float h = t[0];
        float m = h;
#pragma unroll
        for (int off = 16; off > 0; off >>= 1)
            m = fmaxf(m, __shfl_xor_sync(0xFFFFFFFFu, m, off));
        unsigned msk = __ballot_sync(0xFFFFFFFFu, h == m);
        int winner = __ffs(msk) - 1;
        if (lane == winner) {
#pragma unroll
            for (int s = 0; s < TOPK - 1; ++s) t[s] = t[s + 1];
            t[TOPK - 1] = -INFINITY;
        }
        if (lane == 0) g_top[(size_t)w * TOPK + it] = m;
    }
}

// ---------------- kernel 4: entropy over J + weighted partial reduction ----------------
__global__ void __launch_bounds__(256) entropy_kernel() {
    __shared__ float red[256];
    int t = blockIdx.x * 256 + threadIdx.x;  // 0..65535
    int n = t >> 4;
    int k = t & 15;

    float l[NSET];
#pragma unroll
    for (int j = 0; j < NSET; ++j)
        l[j] = g_top[((size_t)j * NROW + n) * TOPK + k] * 100.0f;  // /TEMP

    float mx = l[0];
#pragma unroll
    for (int j = 1; j < NSET; ++j) mx = fmaxf(mx, l[j]);
    float e[NSET], s = 0.0f;
#pragma unroll
    for (int j = 0; j < NSET; ++j) { e[j] = expf(l[j] - mx); s += e[j]; }
    float ls  = logf(s);
    float ent = 0.0f;
#pragma unroll
    for (int j = 0; j < NSET; ++j) {
        float lp = l[j] - mx - ls;
        ent += (e[j] / s) * lp;
    }

    float dsum = (1.0f - powf(0.95f, 16.0f)) / 0.05f;
    float wk   = powf(0.95f, (float)k) / dsum;

    red[threadIdx.x] = ent * wk;
    __syncthreads();
#pragma unroll
    for (int off = 128; off > 0; off >>= 1) {
        if (threadIdx.x < off) red[threadIdx.x] += red[threadIdx.x + off];
        __syncthreads();
    }
    if (threadIdx.x == 0) g_partial[blockIdx.x] = red[0];
}

// ---------------- kernel 5: final reduce ----------------
__global__ void __launch_bounds__(256) finalize_kernel(float* __restrict__ out) {
    __shared__ float red[256];
    red[threadIdx.x] = g_partial[threadIdx.x];
    __syncthreads();
#pragma unroll
    for (int off = 128; off > 0; off >>= 1) {
        if (threadIdx.x < off) red[threadIdx.x] += red[threadIdx.x + off];
        __syncthreads();
    }
    if (threadIdx.x == 0)
        out[0] = red[0] / (float)NROW + logf((float)NSET);
}

// ---------------- launch ----------------
extern "C" void kernel_launch(void* const* d_in, const int* in_sizes, int n_in,
                              void* d_out, int out_size) {
    const float* feature = (const float*)d_in[0];
    const int*   target  = (const int*)d_in[1];
    const float* negs    = (const float*)d_in[2];
    const int*   idxp    = (const int*)d_in[3];
    float*       out     = (float*)d_out;

    // 1) normalize: 4096 + 16384 rows, one warp each, 8 warps/block
    normalize_kernel<<<(NROW + NSET * NROW) / 8, 256>>>(feature, negs);

    // 2) sims GEMM with mask epilogue
    dim3 ggrid(NROW / 64, NROW / 64, NSET);
    gemm_kernel<<<ggrid, 256>>>(target, idxp);

    // 3) top-16 per row: 16384 rows, one warp each
    topk_kernel<<<(NSET * NROW) / 8, 256>>>();

    // 4) entropy + partial sums: 65536 items / 256 per block = 256 blocks
    entropy_kernel<<<256, 256>>>();

    // 5) final scalar
    finalize_kernel<<<1, 256>>>(out);
}

// round 6
// speedup vs baseline: 2.2777x; 2.2777x over previous
#include <cuda_runtime.h>
#include <cuda_bf16.h>
#include <cstdint>
#include <math.h>

#define NROW 4096
#define DIM  128
#define NSET 4
#define TOPK 16

// ---------------- device scratch ----------------
__device__ float g_fn[NROW * DIM];
__device__ float g_nn[NSET * NROW * DIM];
__device__ float g_sims[(size_t)NSET * NROW * NROW];
__device__ float g_top[NSET * NROW * TOPK];
__device__ float g_partial[256];

__device__ __forceinline__ unsigned int f2tf32(float x) {
    unsigned int r;
    asm("cvt.rna.tf32.f32 %0, %1;" : "=r"(r) : "f"(x));
    return r;
}

// ---------------- kernel 1: L2 normalize (one warp per row) ----------------
__global__ void __launch_bounds__(256) normalize_kernel(const float* __restrict__ f,
                                                        const float* __restrict__ negs) {
    int w    = blockIdx.x * 8 + (threadIdx.x >> 5);
    int lane = threadIdx.x & 31;
    const float* src;
    float* dst;
    if (w < NROW) {
        src = f + (size_t)w * DIM;
        dst = g_fn + (size_t)w * DIM;
    } else {
        int r = w - NROW;
        src = negs + (size_t)r * DIM;
        dst = g_nn + (size_t)r * DIM;
    }
    float4 v = ((const float4*)src)[lane];
    float ss = v.x * v.x + v.y * v.y + v.z * v.z + v.w * v.w;
#pragma unroll
    for (int off = 16; off > 0; off >>= 1)
        ss += __shfl_xor_sync(0xFFFFFFFFu, ss, off);
    float inv = 1.0f / fmaxf(sqrtf(ss), 1e-12f);
    v.x *= inv; v.y *= inv; v.z *= inv; v.w *= inv;
    ((float4*)dst)[lane] = v;
}

// ---------------- kernel 2: tf32 tensor-core GEMM + mask epilogue ----------------
// CTA tile 128x128, 8 warps (2x4), each warp 64x32 via m16n8k8 tf32 mma.
// K=128 processed in 4 chunks of 32 (SMEM stays < 48KB static limit).
// grid: (m_tiles=32, n_tiles=32, j=4), block 256.
__global__ void __launch_bounds__(256) gemm_tf32_kernel(const int* __restrict__ targ,
                                                        const int* __restrict__ idxp) {
    __shared__ unsigned int As[128][33];   // [featRow][k]  pitch 33
    __shared__ unsigned int Bs[32][129];   // [k][negRow]   pitch 129

    int j     = blockIdx.z;
    int mbase = blockIdx.x * 128;   // neg rows (output cols)
    int nbase = blockIdx.y * 128;   // feature rows (output rows)
    int tid   = threadIdx.x;
    int wid   = tid >> 5;
    int lane  = tid & 31;
    int g     = lane >> 2;          // group id 0..7
    int c     = lane & 3;           // 0..3

    int wrow = (wid >> 2) * 64;     // warp row offset in tile (0 or 64)
    int wcol = (wid & 3) * 32;      // warp col offset in tile (0..96)

    const float* F = g_fn + (size_t)nbase * DIM;
    const float* N = g_nn + (size_t)j * NROW * DIM + (size_t)mbase * DIM;

    float acc[4][4][4];
#pragma unroll
    for (int mi = 0; mi < 4; ++mi)
#pragma unroll
        for (int ni = 0; ni < 4; ++ni)
#pragma unroll
            for (int r = 0; r < 4; ++r) acc[mi][ni][r] = 0.0f;

#pragma unroll
    for (int ch = 0; ch < 4; ++ch) {  // K chunks of 32
        // ---- cooperative load + tf32 convert ----
        // 128 rows x 32 k-vals per operand = 1024 float4; 4 per thread.
#pragma unroll
        for (int i = 0; i < 4; ++i) {
            int e   = tid + 256 * i;       // 0..1023
            int row = e >> 3;
            int q   = e & 7;               // float4 index within 32 k
            float4 fv = *(const float4*)&F[(size_t)row * DIM + ch * 32 + q * 4];
            float4 nv = *(const float4*)&N[(size_t)row * DIM + ch * 32 + q * 4];
            As[row][q * 4 + 0] = f2tf32(fv.x);
            As[row][q * 4 + 1] = f2tf32(fv.y);
            As[row][q * 4 + 2] = f2tf32(fv.z);
            As[row][q * 4 + 3] = f2tf32(fv.w);
            Bs[q * 4 + 0][row] = f2tf32(nv.x);
            Bs[q * 4 + 1][row] = f2tf32(nv.y);
            Bs[q * 4 + 2][row] = f2tf32(nv.z);
            Bs[q * 4 + 3][row] = f2tf32(nv.w);
        }
        __syncthreads();

        // ---- 4 k8 steps per chunk ----
#pragma unroll
        for (int kk = 0; kk < 32; kk += 8) {
            unsigned int a[4][4], b[4][2];
#pragma unroll
            for (int mi = 0; mi < 4; ++mi) {
                int r0 = wrow + mi * 16;
                a[mi][0] = As[r0 + g][kk + c];
                a[mi][1] = As[r0 + g + 8][kk + c];
                a[mi][2] = As[r0 + g][kk + c + 4];
                a[mi][3] = As[r0 + g + 8][kk + c + 4];
            }
#pragma unroll
            for (int ni = 0; ni < 4; ++ni) {
                int c0 = wcol + ni * 8 + g;
                b[ni][0] = Bs[kk + c][c0];
                b[ni][1] = Bs[kk + c + 4][c0];
            }
#pragma unroll
            for (int mi = 0; mi < 4; ++mi)
#pragma unroll
                for (int ni = 0; ni < 4; ++ni) {
                    asm volatile(
                        "mma.sync.aligned.m16n8k8.row.col.f32.tf32.tf32.f32 "
                        "{%0,%1,%2,%3}, {%4,%5,%6,%7}, {%8,%9}, {%0,%1,%2,%3};"
                        : "+f"(acc[mi][ni][0]), "+f"(acc[mi][ni][1]),
                          "+f"(acc[mi][ni][2]), "+f"(acc[mi][ni][3])
                        : "r"(a[mi][0]), "r"(a[mi][1]), "r"(a[mi][2]), "r"(a[mi][3]),
                          "r"(b[ni][0]), "r"(b[ni][1]));
                }
        }
        __syncthreads();
    }

    // ---- epilogue: mask + store ----
    int  idxv   = *idxp;
    bool domask = (j == idxv);

    // c0,c1 -> row g, cols 2c,2c+1 ; c2,c3 -> row g+8
#pragma unroll
    for (int mi = 0; mi < 4; ++mi) {
#pragma unroll
        for (int half = 0; half < 2; ++half) {
            int n = nbase + wrow + mi * 16 + g + half * 8;
            int tn = domask ? targ[n] : 0;
            size_t rowoff = (((size_t)j * NROW + n) << 12);
#pragma unroll
            for (int ni = 0; ni < 4; ++ni) {
                int m = mbase + wcol + ni * 8 + 2 * c;
                float2 o;
                o.x = acc[mi][ni][half * 2 + 0];
                o.y = acc[mi][ni][half * 2 + 1];
                if (domask) {
                    if (tn == targ[m])     o.x = -1e9f;
                    if (tn == targ[m + 1]) o.y = -1e9f;
                }
                *(float2*)&g_sims[rowoff + m] = o;
            }
        }
    }
}

// ---------------- kernel 3: per-row top-16 (one warp per (j,n) row) ----------------
__global__ void __launch_bounds__(256) topk_kernel() {
    int w    = blockIdx.x * 8 + (threadIdx.x >> 5);
    int lane = threadIdx.x & 31;
    const float* row = g_sims + ((size_t)w << 12);

    float t[TOPK];
#pragma unroll
    for (int s = 0; s < TOPK; ++s) t[s] = -INFINITY;

    for (int i = 0; i < 128; ++i) {
        float v = row[i * 32 + lane];
        if (v > t[TOPK - 1]) {
#pragma unroll
            for (int s = TOPK - 1; s >= 1; --s)
                t[s] = (v > t[s]) ? ((v > t[s - 1]) ? t[s - 1] : v) : t[s];
            t[0] = fmaxf(t[0], v);
        }
    }

    for (int it = 0; it < TOPK; ++it) {
        float h = t[0];
        float m = h;
#pragma unroll
        for (int off = 16; off > 0; off >>= 1)
            m = fmaxf(m, __shfl_xor_sync(0xFFFFFFFFu, m, off));
        unsigned msk = __ballot_sync(0xFFFFFFFFu, h == m);
        int winner = __ffs(msk) - 1;
        if (lane == winner) {
#pragma unroll
            for (int s = 0; s < TOPK - 1; ++s) t[s] = t[s + 1];
            t[TOPK - 1] = -INFINITY;
        }
        if (lane == 0) g_top[(size_t)w * TOPK + it] = m;
    }
}

// ---------------- kernel 4: entropy + weighted partial reduction ----------------
__global__ void __launch_bounds__(256) entropy_kernel() {
    __shared__ float red[256];
    int t = blockIdx.x * 256 + threadIdx.x;
    int n = t >> 4;
    int k = t & 15;

    float l[NSET];
#pragma unroll
    for (int j = 0; j < NSET; ++j)
        l[j] = g_top[((size_t)j * NROW + n) * TOPK + k] * 100.0f;

    float mx = l[0];
#pragma unroll
    for (int j = 1; j < NSET; ++j) mx = fmaxf(mx, l[j]);
    float e[NSET], s = 0.0f;
#pragma unroll
    for (int j = 0; j < NSET; ++j) { e[j] = expf(l[j] - mx); s += e[j]; }
    float ls  = logf(s);
    float ent = 0.0f;
#pragma unroll
    for (int j = 0; j < NSET; ++j) {
        float lp = l[j] - mx - ls;
        ent += (e[j] / s) * lp;
    }

    float dsum = (1.0f - powf(0.95f, 16.0f)) / 0.05f;
    float wk   = powf(0.95f, (float)k) / dsum;

    red[threadIdx.x] = ent * wk;
    __syncthreads();
#pragma unroll
    for (int off = 128; off > 0; off >>= 1) {
        if (threadIdx.x < off) red[threadIdx.x] += red[threadIdx.x + off];
        __syncthreads();
    }
    if (threadIdx.x == 0) g_partial[blockIdx.x] = red[0];
}

// ---------------- kernel 5: final reduce ----------------
__global__ void __launch_bounds__(256) finalize_kernel(float* __restrict__ out) {
    __shared__ float red[256];
    red[threadIdx.x] = g_partial[threadIdx.x];
    __syncthreads();
#pragma unroll
    for (int off = 128; off > 0; off >>= 1) {
        if (threadIdx.x < off) red[threadIdx.x] += red[threadIdx.x + off];
        __syncthreads();
    }
    if (threadIdx.x == 0)
        out[0] = red[0] / (float)NROW + logf((float)NSET);
}

// ---------------- launch ----------------
extern "C" void kernel_launch(void* const* d_in, const int* in_sizes, int n_in,
                              void* d_out, int out_size) {
    const float* feature = (const float*)d_in[0];
    const int*   target  = (const int*)d_in[1];
    const float* negs    = (const float*)d_in[2];
    const int*   idxp    = (const int*)d_in[3];
    float*       out     = (float*)d_out;

    normalize_kernel<<<(NROW + NSET * NROW) / 8, 256>>>(feature, negs);

    dim3 ggrid(NROW / 128, NROW / 128, NSET);
    gemm_tf32_kernel<<<ggrid, 256>>>(target, idxp);

    topk_kernel<<<(NSET * NROW) / 8, 256>>>();

    entropy_kernel<<<256, 256>>>();

    finalize_kernel<<<1, 256>>>(out);
}